// round 6
// baseline (speedup 1.0000x reference)
#include <cuda_runtime.h>
#include <math.h>
#include <stdint.h>

#define NEL 32
#define NUP 16
#define NI  32
#define NL  16
#define NK  16
#define H1  128
#define H2  4
#define FLEN 392
#define GRID_MAIN 128
#define GRID_ALL  132          // +4 dh blocks

#define NSTAGE 3
#define W_BYTES   (FLEN * 128)          // [392 rows][32 floats, xor-swizzled 16B chunks]
#define BIAS_OFF  W_BYTES
#define STAGE_BYTES (W_BYTES + 128)
#define DYN_BYTES (NSTAGE * STAGE_BYTES)

// ---- device-global state (no allocation allowed) ----
__device__ float g_sh[2][NEL][H1];
__device__ float g_rN[NEL][NI];
__device__ float g_dg[NL][NEL][8];        // per-layer dg_up(4)|dg_dn(4)
__device__ float g_phi[NK][2][16][16];
__device__ float g_det[NK][2];
__device__ unsigned g_bar8[NL + 2][8][32]; // 8 sub-counters, 128B apart
__device__ unsigned g_dhbar[NL];           // dh-producer flags (target 4)

// ---------------- cp.async ----------------
__device__ __forceinline__ void cp_async16(uint32_t saddr, const void* gptr) {
    asm volatile("cp.async.cg.shared.global [%0], [%1], 16;" :: "r"(saddr), "l"(gptr));
}
__device__ __forceinline__ void cp_commit() { asm volatile("cp.async.commit_group;"); }
#define CP_WAIT(N) asm volatile("cp.async.wait_group %0;" :: "n"(N))

// ---------------- sync primitives ----------------
__device__ __forceinline__ unsigned ld_acq(const unsigned* p) {
    unsigned v;
    asm volatile("ld.acquire.gpu.global.u32 %0, [%1];" : "=r"(v) : "l"(p) : "memory");
    return v;
}
__device__ __forceinline__ void red_rel_add1(unsigned* p) {
    asm volatile("red.release.gpu.global.add.u32 [%0], 1;" :: "l"(p) : "memory");
}
__device__ __forceinline__ void bar_arrive(int idx) {
    __syncthreads();
    if (threadIdx.x == 0) red_rel_add1(&g_bar8[idx][blockIdx.x & 7][0]);
}
__device__ __forceinline__ unsigned bar_sum(int idx) {
    unsigned s0 = ld_acq(&g_bar8[idx][0][0]);
    unsigned s1 = ld_acq(&g_bar8[idx][1][0]);
    unsigned s2 = ld_acq(&g_bar8[idx][2][0]);
    unsigned s3 = ld_acq(&g_bar8[idx][3][0]);
    unsigned s4 = ld_acq(&g_bar8[idx][4][0]);
    unsigned s5 = ld_acq(&g_bar8[idx][5][0]);
    unsigned s6 = ld_acq(&g_bar8[idx][6][0]);
    unsigned s7 = ld_acq(&g_bar8[idx][7][0]);
    return ((s0 + s1) + (s2 + s3)) + ((s4 + s5) + (s6 + s7));
}
__device__ __forceinline__ void bar_wait(int idx, unsigned target) {
    if (threadIdx.x == 0) { while (bar_sum(idx) < target) { } }
    __syncthreads();
}
// wait for previous main layer (if l>0) AND the dh producers' dg for layer l
__device__ __forceinline__ void layer_wait(int l) {
    if (threadIdx.x == 0) {
        for (;;) {
            bool ok = (l == 0) || (bar_sum(l - 1) >= GRID_MAIN);
            if (ok && ld_acq(&g_dhbar[l]) >= 4) break;
        }
    }
    __syncthreads();
}

// ---------------------------------------------------------------------------
// Preprocess: sh0 + rN, zero barrier counters (every replay)
// ---------------------------------------------------------------------------
__global__ void pre_kernel(const float* __restrict__ ep,
                           const float* __restrict__ nuc) {
    int t = threadIdx.x;
    for (int p = t; p < (NL + 2) * 8; p += blockDim.x) g_bar8[p >> 3][p & 7][0] = 0;
    if (t < NL) g_dhbar[t] = 0;
    for (int p = t; p < NEL * NI; p += blockDim.x) {
        int j = p >> 5, m = p & 31;
        float dx = ep[j * 3 + 0] - nuc[m * 3 + 0];
        float dy = ep[j * 3 + 1] - nuc[m * 3 + 1];
        float dz = ep[j * 3 + 2] - nuc[m * 3 + 2];
        float r  = sqrtf(dx * dx + dy * dy + dz * dz);
        g_sh[0][j][m * 3 + 0] = dx;
        g_sh[0][j][m * 3 + 1] = dy;
        g_sh[0][j][m * 3 + 2] = dz;
        g_sh[0][j][3 * NI + m] = r;
        g_rN[j][m] = r;
    }
}

// ---------------------------------------------------------------------------
// Fill one weight stage (single-stream weights + bias). XOR-swizzled so the
// consumer (lane = row) gets conflict-free LDS.128.
// ---------------------------------------------------------------------------
__device__ __forceinline__ void fill_stage(
    uint32_t sb, int l, int n, int og, int t, int fs, int c4,
    const float* __restrict__ v, const float* __restrict__ b)
{
    const char* vbase = (const char*)(v + (((size_t)l * NEL + n) * FLEN) * H1 + og * 32);
    const uint32_t dcol = (uint32_t)((c4 ^ (fs & 7)) * 16);
#pragma unroll
    for (int i = 0; i < 12; i++) {
        int row = fs + 32 * i;
        cp_async16(sb + row * 128 + dcol, vbase + (size_t)row * 512 + c4 * 16);
    }
    if (fs < 8) {
        int row = fs + 384;
        cp_async16(sb + row * 128 + dcol, vbase + (size_t)row * 512 + c4 * 16);
    }
    if (t < 8)
        cp_async16(sb + BIAS_OFF + t * 16,
                   b + ((size_t)l * NEL + n) * H1 + og * 32 + t * 4);
}

// ---------------------------------------------------------------------------
// Fused persistent kernel.
//  blocks 0..127 : single-stream layers + phi + det + out  (n = b>>2, og = b&3)
//  blocks 128..131: dh chain producers (registers only), publish g_dg + flags
// ---------------------------------------------------------------------------
__global__ void __launch_bounds__(256, 1) fused_kernel(
    const float* __restrict__ ep, const float* __restrict__ v,
    const float* __restrict__ b,  const float* __restrict__ w,
    const float* __restrict__ c,  const float* __restrict__ fw,
    const float* __restrict__ fb, const float* __restrict__ pi,
    const float* __restrict__ sigma, const float* __restrict__ omega,
    float* __restrict__ out)
{
    extern __shared__ char dyn[];
    __shared__ float fsh[FLEN];
    __shared__ float A[16][17];
    __shared__ float fac[16];
    __shared__ int   pivs;
    __shared__ float dsh;

    const int t = threadIdx.x;

    // ================= dh producer blocks =================
    if (blockIdx.x >= GRID_MAIN) {
        const int i  = (blockIdx.x - GRID_MAIN) * 8 + (t >> 5);  // electron
        const int j  = t & 31;
        const int lane = t & 31;
        float4 d4;
        {
            float dx = ep[i * 3 + 0] - ep[j * 3 + 0];
            float dy = ep[i * 3 + 1] - ep[j * 3 + 1];
            float dz = ep[i * 3 + 2] - ep[j * 3 + 2];
            d4 = make_float4(dx, dy, dz, sqrtf(dx * dx + dy * dy + dz * dz));
        }
#pragma unroll 1
        for (int l = 0; l < NL; l++) {
            // prefetch update weights (independent of means)
            float4 w0, w1, w2, w3, cc4;
            if (l < NL - 1) {
                const float* wp = w + ((size_t)(l * NEL + i) * NEL + j) * 16;
                w0 = *reinterpret_cast<const float4*>(wp);
                w1 = *reinterpret_cast<const float4*>(wp + 4);
                w2 = *reinterpret_cast<const float4*>(wp + 8);
                w3 = *reinterpret_cast<const float4*>(wp + 12);
                cc4 = *reinterpret_cast<const float4*>(
                    c + ((size_t)(l * NEL + i) * NEL + j) * 4);
            }
            // spin-split means via half-warp shfl (lanes 0..15 = up, 16..31 = dn)
            float4 s = d4;
#pragma unroll
            for (int off = 8; off; off >>= 1) {
                s.x += __shfl_down_sync(0xffffffffu, s.x, off, 16);
                s.y += __shfl_down_sync(0xffffffffu, s.y, off, 16);
                s.z += __shfl_down_sync(0xffffffffu, s.z, off, 16);
                s.w += __shfl_down_sync(0xffffffffu, s.w, off, 16);
            }
            if (lane == 0) {
                float4 m = make_float4(s.x / 16, s.y / 16, s.z / 16, s.w / 16);
                __stcg(reinterpret_cast<float4*>(&g_dg[l][i][0]), m);
            }
            if (lane == 16) {
                float4 m = make_float4(s.x / 16, s.y / 16, s.z / 16, s.w / 16);
                __stcg(reinterpret_cast<float4*>(&g_dg[l][i][4]), m);
            }
            __syncthreads();
            if (t == 0) red_rel_add1(&g_dhbar[l]);
            // update dh (register-resident)
            if (l < NL - 1) {
                float o0 = d4.x * w0.x + d4.y * w1.x + d4.z * w2.x + d4.w * w3.x;
                float o1 = d4.x * w0.y + d4.y * w1.y + d4.z * w2.y + d4.w * w3.y;
                float o2 = d4.x * w0.z + d4.y * w1.z + d4.z * w2.z + d4.w * w3.z;
                float o3 = d4.x * w0.w + d4.y * w1.w + d4.z * w2.w + d4.w * w3.w;
                d4.x = tanhf(o0 + cc4.x) + d4.x;
                d4.y = tanhf(o1 + cc4.y) + d4.y;
                d4.z = tanhf(o2 + cc4.z) + d4.z;
                d4.w = tanhf(o3 + cc4.w) + d4.w;
            }
        }
        return;
    }

    // ================= main blocks =================
    const int n    = blockIdx.x >> 2;
    const int og   = blockIdx.x & 3;
    const int c4   = t & 7;
    const int fs   = t >> 3;
    const int lane = t & 31, wp = t >> 5;
    const uint32_t dyn_s = (uint32_t)__cvta_generic_to_shared(dyn);

#pragma unroll
    for (int s = 0; s < NSTAGE; s++) {
        fill_stage(dyn_s + s * STAGE_BYTES, s, n, og, t, fs, c4, v, b);
        cp_commit();
    }

#pragma unroll 1
    for (int l = 0; l < NL; l++) {
        const int stage = l % NSTAGE;
        const char* sp = dyn + stage * STAGE_BYTES;

        CP_WAIT(NSTAGE - 1);
        layer_wait(l);
        const int cur = l & 1, nxt = cur ^ 1;

        // ---- feature vector ----
        if (t < H1) {
            float s = 0.f;
#pragma unroll
            for (int r = 0; r < NUP; r++) s += __ldcg(&g_sh[cur][r][t]);
            fsh[H1 + t] = s * (1.0f / 16);
            fsh[t] = __ldcg(&g_sh[cur][n][t]);
        } else {
            int o = t - H1;
            float s = 0.f;
#pragma unroll
            for (int r = NUP; r < NEL; r++) s += __ldcg(&g_sh[cur][r][o]);
            fsh[2 * H1 + o] = s * (1.0f / 16);
        }
        if (t < 8) fsh[3 * H1 + t] = __ldcg(&g_dg[l][n][t]);
        __syncthreads();

        // ---- matvec: warp wp owns output cols [4wp, 4wp+4), lane = row slice ----
        const float4* wst = (const float4*)sp;
        const int scol = wp ^ (lane & 7);
        float4 acc = make_float4(0.f, 0.f, 0.f, 0.f);
#pragma unroll
        for (int i = 0; i < 12; i++) {
            int r = lane + 32 * i;
            float s = fsh[r];
            float4 wr = wst[r * 8 + scol];
            acc.x += s * wr.x; acc.y += s * wr.y;
            acc.z += s * wr.z; acc.w += s * wr.w;
        }
        if (lane < 8) {
            int r = lane + 384;
            float s = fsh[r];
            float4 wr = wst[r * 8 + scol];
            acc.x += s * wr.x; acc.y += s * wr.y;
            acc.z += s * wr.z; acc.w += s * wr.w;
        }
#pragma unroll
        for (int off = 16; off; off >>= 1) {
            acc.x += __shfl_down_sync(0xffffffffu, acc.x, off);
            acc.y += __shfl_down_sync(0xffffffffu, acc.y, off);
            acc.z += __shfl_down_sync(0xffffffffu, acc.z, off);
            acc.w += __shfl_down_sync(0xffffffffu, acc.w, off);
        }
        if (lane == 0) {
            const float4 bias = *(const float4*)(sp + BIAS_OFF + wp * 16);
            int o = og * 32 + wp * 4;
            float4 a;
            a.x = tanhf(acc.x + bias.x) + fsh[o + 0];
            a.y = tanhf(acc.y + bias.y) + fsh[o + 1];
            a.z = tanhf(acc.z + bias.z) + fsh[o + 2];
            a.w = tanhf(acc.w + bias.w) + fsh[o + 3];
            __stcg(reinterpret_cast<float4*>(&g_sh[nxt][n][o]), a);
        }
        bar_arrive(l);

        if (l + NSTAGE < NL)
            fill_stage(dyn_s + stage * STAGE_BYTES, l + NSTAGE, n, og, t, fs, c4, v, b);
        cp_commit();
    }

    // ================= phi (diagonal 16x16 blocks only) =================
    bar_wait(NL - 1, GRID_MAIN);
    {
        const int k    = blockIdx.x >> 3;
        const int i    = (blockIdx.x & 7) * 4 + (t >> 6);
        const int spin = i >> 4;
        const int tl   = t & 63;
        const int jl   = tl >> 2, s = tl & 3;
        const int j    = spin * 16 + jl;
        const float* fwp = fw + (size_t)(k * NEL + i) * H1;
        float dot = 0.f;
#pragma unroll
        for (int q = 0; q < 32; q++)
            dot += fwp[s + 4 * q] * __ldcg(&g_sh[0][j][s + 4 * q]);
        const float* pip = pi    + (size_t)(k * NEL + i) * NI;
        const float* sgp = sigma + (size_t)(k * NEL + i) * NI;
        float env = 0.f;
#pragma unroll
        for (int q = 0; q < 8; q++) {
            int m = s * 8 + q;
            env += pip[m] * __expf(-fabsf(sgp[m]) * g_rN[j][m]);
        }
        dot += __shfl_down_sync(0xffffffffu, dot, 2, 4);
        dot += __shfl_down_sync(0xffffffffu, dot, 1, 4);
        env += __shfl_down_sync(0xffffffffu, env, 2, 4);
        env += __shfl_down_sync(0xffffffffu, env, 1, 4);
        if (s == 0)
            __stcg(&g_phi[k][spin][i & 15][jl], (dot + fb[k * NEL + i]) * env);
    }
    bar_arrive(NL);

    // ================= determinants (blocks 0..31) =================
    if (blockIdx.x < 32) {
        bar_wait(NL, GRID_MAIN);
        const int k = blockIdx.x >> 1, spin = blockIdx.x & 1;
        const int r = t >> 4, cc = t & 15;
        A[r][cc] = __ldcg(&g_phi[k][spin][r][cc]);
        if (t == 0) dsh = 1.0f;
        __syncthreads();
        for (int p = 0; p < 16; p++) {
            if (t == 0) {
                int best = p;
                float bv = fabsf(A[p][p]);
                for (int rr = p + 1; rr < 16; rr++) {
                    float v2 = fabsf(A[rr][p]);
                    if (v2 > bv) { bv = v2; best = rr; }
                }
                pivs = best;
                if (best != p) dsh = -dsh;
            }
            __syncthreads();
            int piv = pivs;
            if (piv != p && t < 16) {
                float tmp = A[p][t]; A[p][t] = A[piv][t]; A[piv][t] = tmp;
            }
            __syncthreads();
            if (t < 16 && t > p) fac[t] = A[t][p] / A[p][p];
            if (t == 0) dsh *= A[p][p];
            __syncthreads();
            if (r > p && cc > p) A[r][cc] -= fac[r] * A[p][cc];
            __syncthreads();
        }
        if (t == 0) __stcg(&g_det[k][spin], dsh);
        bar_arrive(NL + 1);
    }

    // ================= final reduction (block 0) =================
    if (blockIdx.x == 0) {
        bar_wait(NL + 1, 32);
        if (t < 32) {
            float vv = (t < NK) ? omega[t] * __ldcg(&g_det[t][0]) * __ldcg(&g_det[t][1])
                                : 0.0f;
#pragma unroll
            for (int off = 16; off; off >>= 1)
                vv += __shfl_down_sync(0xffffffffu, vv, off);
            if (t == 0) out[0] = vv;
        }
    }
}

extern "C" void kernel_launch(void* const* d_in, const int* in_sizes, int n_in,
                              void* d_out, int out_size) {
    const float* ep    = (const float*)d_in[0];
    const float* nuc   = (const float*)d_in[1];
    const float* v     = (const float*)d_in[2];
    const float* b     = (const float*)d_in[3];
    const float* w     = (const float*)d_in[4];
    const float* c     = (const float*)d_in[5];
    const float* fw    = (const float*)d_in[6];
    const float* fb    = (const float*)d_in[7];
    const float* pi    = (const float*)d_in[8];
    const float* sigma = (const float*)d_in[9];
    const float* omega = (const float*)d_in[10];

    cudaFuncSetAttribute(fused_kernel,
                         cudaFuncAttributeMaxDynamicSharedMemorySize, DYN_BYTES);
    pre_kernel<<<1, 256>>>(ep, nuc);
    fused_kernel<<<GRID_ALL, 256, DYN_BYTES>>>(ep, v, b, w, c, fw, fb, pi, sigma,
                                               omega, (float*)d_out);
}